// round 2
// baseline (speedup 1.0000x reference)
#include <cuda_runtime.h>
#include <math.h>

#define SLEN   1024
#define DMODEL 1024
#define NHEAD  16
#define DHEAD  64
#define NC     64      // number of compression slots C
#define CHUNK  64
#define NCHUNK 16

// ---------------- global scratch (no allocation allowed) ----------------
__device__ float g_Q[SLEN*DMODEL];
__device__ float g_K[SLEN*DMODEL];
__device__ float g_V[SLEN*DMODEL];
__device__ float g_O[SLEN*DMODEL];
__device__ float g_cw[NHEAD*NC*SLEN];        // [h][c][s]
__device__ float g_rowmax[NHEAD*NC];
__device__ float g_Tk[NHEAD*NCHUNK*NC*DHEAD];
__device__ float g_Tv[NHEAD*NCHUNK*NC*DHEAD];
__device__ float g_Tn[NHEAD*NCHUNK*NC];
__device__ float g_A0k[NHEAD*NCHUNK*NC*DHEAD];
__device__ float g_A0v[NHEAD*NCHUNK*NC*DHEAD];
__device__ float g_N0[NHEAD*NCHUNK*NC];

// ---------------- big GEMM: C[m,n] = sum_k A[m,k]*B[n,k] + bias[n] ------
// 128x128 tile, 8x8 microtile, 256 threads.
__device__ __forceinline__ void gemm128_nt(const float* __restrict__ A,
                                           const float* __restrict__ B,
                                           const float* __restrict__ bias,
                                           float* __restrict__ Cmat)
{
    __shared__ float As[16][132];
    __shared__ float Bs[16][132];
    const int tid = threadIdx.x;
    const int tx = tid & 15;
    const int ty = tid >> 4;
    const int m0 = blockIdx.y << 7;
    const int n0 = blockIdx.x << 7;
    const int lr = tid >> 2;           // 0..63
    const int lk = (tid & 3) << 2;     // 0,4,8,12

    float acc[8][8];
#pragma unroll
    for (int i = 0; i < 8; ++i)
#pragma unroll
        for (int j = 0; j < 8; ++j) acc[i][j] = 0.f;

    const float* Aptr = A + (size_t)(m0 + lr) * DMODEL + lk;
    const float* Bptr = B + (size_t)(n0 + lr) * DMODEL + lk;

    for (int k0 = 0; k0 < DMODEL; k0 += 16) {
        float4 a0 = *(const float4*)(Aptr + k0);
        float4 a1 = *(const float4*)(Aptr + 64 * DMODEL + k0);
        float4 b0 = *(const float4*)(Bptr + k0);
        float4 b1 = *(const float4*)(Bptr + 64 * DMODEL + k0);
        __syncthreads();
        As[lk+0][lr]    = a0.x; As[lk+1][lr]    = a0.y; As[lk+2][lr]    = a0.z; As[lk+3][lr]    = a0.w;
        As[lk+0][lr+64] = a1.x; As[lk+1][lr+64] = a1.y; As[lk+2][lr+64] = a1.z; As[lk+3][lr+64] = a1.w;
        Bs[lk+0][lr]    = b0.x; Bs[lk+1][lr]    = b0.y; Bs[lk+2][lr]    = b0.z; Bs[lk+3][lr]    = b0.w;
        Bs[lk+0][lr+64] = b1.x; Bs[lk+1][lr+64] = b1.y; Bs[lk+2][lr+64] = b1.z; Bs[lk+3][lr+64] = b1.w;
        __syncthreads();
#pragma unroll
        for (int kk = 0; kk < 16; ++kk) {
            float4 av0 = *(const float4*)&As[kk][ty << 3];
            float4 av1 = *(const float4*)&As[kk][(ty << 3) + 4];
            float4 bv0 = *(const float4*)&Bs[kk][tx << 3];
            float4 bv1 = *(const float4*)&Bs[kk][(tx << 3) + 4];
            float ar[8] = {av0.x, av0.y, av0.z, av0.w, av1.x, av1.y, av1.z, av1.w};
            float br[8] = {bv0.x, bv0.y, bv0.z, bv0.w, bv1.x, bv1.y, bv1.z, bv1.w};
#pragma unroll
            for (int i = 0; i < 8; ++i)
#pragma unroll
                for (int j = 0; j < 8; ++j)
                    acc[i][j] = fmaf(ar[i], br[j], acc[i][j]);
        }
    }
#pragma unroll
    for (int i = 0; i < 8; ++i) {
        int m = m0 + (ty << 3) + i;
#pragma unroll
        for (int j = 0; j < 8; ++j) {
            int n = n0 + (tx << 3) + j;
            Cmat[(size_t)m * DMODEL + n] = acc[i][j] + bias[n];
        }
    }
}

__global__ __launch_bounds__(256) void gemm_qkv_kernel(
    const float* __restrict__ x,
    const float* __restrict__ Wq, const float* __restrict__ bq,
    const float* __restrict__ Wk, const float* __restrict__ bk,
    const float* __restrict__ Wv, const float* __restrict__ bv)
{
    int z = blockIdx.z;
    const float* W = (z == 0) ? Wq : ((z == 1) ? Wk : Wv);
    const float* b = (z == 0) ? bq : ((z == 1) ? bk : bv);
    float* out = (z == 0) ? g_Q : ((z == 1) ? g_K : g_V);
    gemm128_nt(x, W, b, out);
}

__global__ __launch_bounds__(256) void gemm_out_kernel(
    const float* __restrict__ Wo, const float* __restrict__ bo,
    float* __restrict__ out)
{
    gemm128_nt(g_O, Wo, bo, out);
}

// ---------------- rowmax init ----------------
__global__ void init_rowmax_kernel() { g_rowmax[threadIdx.x] = -INFINITY; }

__device__ __forceinline__ void atomicMaxFloat(float* addr, float v)
{
    if (v >= 0.f) atomicMax((int*)addr, __float_as_int(v));
    else          atomicMin((unsigned int*)addr, __float_as_uint(v));
}

// ---------------- cw_raw[h,c,s] = qc_h[c,:] . k[s,:] -------------------
__global__ __launch_bounds__(256) void cw_kernel(const float* __restrict__ q_c)
{
    __shared__ float qcs[NC][DHEAD + 1];
    __shared__ float Ks[CHUNK][DHEAD + 1];
    __shared__ float red[NC][17];
    const int h = blockIdx.y;
    const int s0 = blockIdx.x * CHUNK;
    const int tid = threadIdx.x;
    const int tx = tid & 15, ty = tid >> 4;

    for (int e = tid; e < NC * DHEAD; e += 256) {
        int r = e >> 6, d = e & 63;
        qcs[r][d] = q_c[(size_t)r * DMODEL + h * DHEAD + d];
        Ks[r][d]  = g_K[(size_t)(s0 + r) * DMODEL + h * DHEAD + d];
    }
    __syncthreads();

    float acc[4][4];
#pragma unroll
    for (int i = 0; i < 4; ++i)
#pragma unroll
        for (int j = 0; j < 4; ++j) acc[i][j] = 0.f;

    for (int d = 0; d < DHEAD; ++d) {
        float ar[4], br[4];
#pragma unroll
        for (int i = 0; i < 4; ++i) ar[i] = qcs[(ty << 2) + i][d];
#pragma unroll
        for (int j = 0; j < 4; ++j) br[j] = Ks[(tx << 2) + j][d];
#pragma unroll
        for (int i = 0; i < 4; ++i)
#pragma unroll
            for (int j = 0; j < 4; ++j) acc[i][j] = fmaf(ar[i], br[j], acc[i][j]);
    }

    float mx[4];
#pragma unroll
    for (int i = 0; i < 4; ++i) {
        mx[i] = -INFINITY;
        int c = (ty << 2) + i;
#pragma unroll
        for (int j = 0; j < 4; ++j) {
            int t = (tx << 2) + j;
            g_cw[((size_t)h * NC + c) * SLEN + s0 + t] = acc[i][j];
            mx[i] = fmaxf(mx[i], acc[i][j]);
        }
        red[c][tx] = mx[i];
    }
    __syncthreads();
    if (tid < NC) {
        float m = red[tid][0];
#pragma unroll
        for (int t = 1; t < 16; ++t) m = fmaxf(m, red[tid][t]);
        atomicMaxFloat(&g_rowmax[h * NC + tid], m);
    }
}

// ---------------- cw = exp(cw_raw - rowmax) ----------------------------
__global__ __launch_bounds__(256) void exp_kernel()
{
    int i = blockIdx.x * 256 + threadIdx.x;   // total = NHEAD*NC*SLEN
    g_cw[i] = expf(g_cw[i] - g_rowmax[i >> 10]);
}

// ---------------- chunk totals: T = cw_chunk @ [K|V]_chunk -------------
struct ChunkSmem {
    float cws[NC][CHUNK + 1];
    float Ks[CHUNK][DHEAD + 1];
    float Vs[CHUNK][DHEAD + 1];
};

__global__ __launch_bounds__(256) void chunksum_kernel()
{
    extern __shared__ char smem_raw[];
    ChunkSmem& sm = *(ChunkSmem*)smem_raw;
    const int h = blockIdx.y, ch = blockIdx.x;
    const int s0 = ch * CHUNK;
    const int tid = threadIdx.x;
    const int tx = tid & 15, ty = tid >> 4;

    for (int e = tid; e < NC * CHUNK; e += 256) {
        int r = e >> 6, d = e & 63;
        sm.cws[r][d] = g_cw[((size_t)h * NC + r) * SLEN + s0 + d];
        sm.Ks[r][d]  = g_K[(size_t)(s0 + r) * DMODEL + h * DHEAD + d];
        sm.Vs[r][d]  = g_V[(size_t)(s0 + r) * DMODEL + h * DHEAD + d];
    }
    __syncthreads();

    float ak[4][4], av[4][4];
#pragma unroll
    for (int i = 0; i < 4; ++i)
#pragma unroll
        for (int j = 0; j < 4; ++j) { ak[i][j] = 0.f; av[i][j] = 0.f; }

    for (int t = 0; t < CHUNK; ++t) {
        float ar[4], bk[4], bv[4];
#pragma unroll
        for (int i = 0; i < 4; ++i) ar[i] = sm.cws[(ty << 2) + i][t];
#pragma unroll
        for (int j = 0; j < 4; ++j) { bk[j] = sm.Ks[t][(tx << 2) + j]; bv[j] = sm.Vs[t][(tx << 2) + j]; }
#pragma unroll
        for (int i = 0; i < 4; ++i)
#pragma unroll
            for (int j = 0; j < 4; ++j) {
                ak[i][j] = fmaf(ar[i], bk[j], ak[i][j]);
                av[i][j] = fmaf(ar[i], bv[j], av[i][j]);
            }
    }
    const size_t base = ((size_t)(h * NCHUNK + ch) * NC) * DHEAD;
#pragma unroll
    for (int i = 0; i < 4; ++i) {
        int c = (ty << 2) + i;
#pragma unroll
        for (int j = 0; j < 4; ++j) {
            int d = (tx << 2) + j;
            g_Tk[base + (size_t)c * DHEAD + d] = ak[i][j];
            g_Tv[base + (size_t)c * DHEAD + d] = av[i][j];
        }
    }
    if (tid < NC) {
        float s = 0.f;
#pragma unroll
        for (int t = 0; t < CHUNK; ++t) s += sm.cws[tid][t];
        g_Tn[(size_t)(h * NCHUNK + ch) * NC + tid] = s;
    }
}

// ---------------- exclusive prefix over chunks -------------------------
__global__ __launch_bounds__(256) void prefix_kernel()
{
    const int h = blockIdx.x;
    const int tid = threadIdx.x;
    for (int e = tid; e < NC * DHEAD; e += 256) {
        float rk = 0.f, rv = 0.f;
        for (int ch = 0; ch < NCHUNK; ++ch) {
            size_t idx = ((size_t)(h * NCHUNK + ch) * NC) * DHEAD + e;
            g_A0k[idx] = rk; rk += g_Tk[idx];
            g_A0v[idx] = rv; rv += g_Tv[idx];
        }
    }
    for (int e = tid; e < NC; e += 256) {
        float rn = 0.f;
        for (int ch = 0; ch < NCHUNK; ++ch) {
            size_t idx = (size_t)(h * NCHUNK + ch) * NC + e;
            g_N0[idx] = rn; rn += g_Tn[idx];
        }
    }
}

// ---------------- per-(head,chunk) attention ---------------------------
struct K6Smem {
    float Qs[CHUNK][DHEAD + 1];
    float Ks[CHUNK][DHEAD + 1];
    float Vs[CHUNK][DHEAD + 1];
    float cws[NC][CHUNK + 1];     // cw[c][t]
    float ncs[NC][CHUNK + 1];     // N[c][s] (inclusive)
    float A0k[NC][DHEAD + 1];
    float A0v[NC][DHEAD + 1];
    float G[CHUNK][CHUNK + 1];    // masked q.k, later reused for W
    float P[CHUNK][NC + 1];       // scores -> p
    float n0v[NC];
};

__global__ __launch_bounds__(256) void attn_kernel(const float* __restrict__ beta)
{
    extern __shared__ char smem_raw[];
    K6Smem& sm = *(K6Smem*)smem_raw;
    const int h = blockIdx.y, ch = blockIdx.x;
    const int s0 = ch * CHUNK;
    const int tid = threadIdx.x;
    const int tx = tid & 15, ty = tid >> 4;
    const float qscale = 0.125f * expf(-beta[h]);

    const size_t abase = ((size_t)(h * NCHUNK + ch) * NC) * DHEAD;
    for (int e = tid; e < CHUNK * DHEAD; e += 256) {
        int r = e >> 6, d = e & 63;
        sm.Qs[r][d]  = g_Q[(size_t)(s0 + r) * DMODEL + h * DHEAD + d] * qscale;
        sm.Ks[r][d]  = g_K[(size_t)(s0 + r) * DMODEL + h * DHEAD + d];
        sm.Vs[r][d]  = g_V[(size_t)(s0 + r) * DMODEL + h * DHEAD + d];
        sm.cws[r][d] = g_cw[((size_t)h * NC + r) * SLEN + s0 + d];
        sm.A0k[r][d] = g_A0k[abase + e];
        sm.A0v[r][d] = g_A0v[abase + e];
    }
    if (tid < NC) sm.n0v[tid] = g_N0[(size_t)(h * NCHUNK + ch) * NC + tid];
    __syncthreads();

    // N[c][s] inclusive cumsum (threads 0..63, serial over 64)
    if (tid < NC) {
        float run = sm.n0v[tid];
#pragma unroll
        for (int t = 0; t < CHUNK; ++t) { run += sm.cws[tid][t]; sm.ncs[tid][t] = run; }
    }

    // G[s][t] = (t<=s) ? Qs[s].Ks[t] : 0
    {
        float acc[4][4];
#pragma unroll
        for (int i = 0; i < 4; ++i)
#pragma unroll
            for (int j = 0; j < 4; ++j) acc[i][j] = 0.f;
        for (int d = 0; d < DHEAD; ++d) {
            float ar[4], br[4];
#pragma unroll
            for (int i = 0; i < 4; ++i) ar[i] = sm.Qs[(ty << 2) + i][d];
#pragma unroll
            for (int j = 0; j < 4; ++j) br[j] = sm.Ks[(tx << 2) + j][d];
#pragma unroll
            for (int i = 0; i < 4; ++i)
#pragma unroll
                for (int j = 0; j < 4; ++j) acc[i][j] = fmaf(ar[i], br[j], acc[i][j]);
        }
#pragma unroll
        for (int i = 0; i < 4; ++i) {
            int s = (ty << 2) + i;
#pragma unroll
            for (int j = 0; j < 4; ++j) {
                int t = (tx << 2) + j;
                sm.G[s][t] = (t <= s) ? acc[i][j] : 0.f;
            }
        }
    }
    __syncthreads();

    // P[s][c] = (Qs[s].A0k[c] + sum_t G[s][t]*cw[c][t]) / N[c][s]
    {
        float acc[4][4];
#pragma unroll
        for (int i = 0; i < 4; ++i)
#pragma unroll
            for (int j = 0; j < 4; ++j) acc[i][j] = 0.f;
        for (int d = 0; d < DHEAD; ++d) {
            float ar[4], br[4];
#pragma unroll
            for (int i = 0; i < 4; ++i) ar[i] = sm.Qs[(ty << 2) + i][d];
#pragma unroll
            for (int j = 0; j < 4; ++j) br[j] = sm.A0k[(tx << 2) + j][d];
#pragma unroll
            for (int i = 0; i < 4; ++i)
#pragma unroll
                for (int j = 0; j < 4; ++j) acc[i][j] = fmaf(ar[i], br[j], acc[i][j]);
        }
        for (int t = 0; t < CHUNK; ++t) {
            float ar[4], br[4];
#pragma unroll
            for (int i = 0; i < 4; ++i) ar[i] = sm.G[(ty << 2) + i][t];
#pragma unroll
            for (int j = 0; j < 4; ++j) br[j] = sm.cws[(tx << 2) + j][t];
#pragma unroll
            for (int i = 0; i < 4; ++i)
#pragma unroll
                for (int j = 0; j < 4; ++j) acc[i][j] = fmaf(ar[i], br[j], acc[i][j]);
        }
#pragma unroll
        for (int i = 0; i < 4; ++i) {
            int s = (ty << 2) + i;
#pragma unroll
            for (int j = 0; j < 4; ++j) {
                int c = (tx << 2) + j;
                sm.P[s][c] = acc[i][j] / sm.ncs[c][s];
            }
        }
    }
    __syncthreads();

    // softmax over c per row s, then p = sw / N[c][s]
    if (tid < CHUNK) {
        int s = tid;
        float m = -INFINITY;
#pragma unroll
        for (int c = 0; c < NC; ++c) m = fmaxf(m, sm.P[s][c]);
        float sum = 0.f;
#pragma unroll
        for (int c = 0; c < NC; ++c) { float e = expf(sm.P[s][c] - m); sm.P[s][c] = e; sum += e; }
        float inv = 1.f / sum;
#pragma unroll
        for (int c = 0; c < NC; ++c) sm.P[s][c] = sm.P[s][c] * inv / sm.ncs[c][s];
    }
    __syncthreads();

    // W[s][t] = (t<=s) ? sum_c P[s][c]*cw[c][t] : 0   (into G)
    {
        float acc[4][4];
#pragma unroll
        for (int i = 0; i < 4; ++i)
#pragma unroll
            for (int j = 0; j < 4; ++j) acc[i][j] = 0.f;
        for (int c = 0; c < NC; ++c) {
            float ar[4], br[4];
#pragma unroll
            for (int i = 0; i < 4; ++i) ar[i] = sm.P[(ty << 2) + i][c];
#pragma unroll
            for (int j = 0; j < 4; ++j) br[j] = sm.cws[c][(tx << 2) + j];
#pragma unroll
            for (int i = 0; i < 4; ++i)
#pragma unroll
                for (int j = 0; j < 4; ++j) acc[i][j] = fmaf(ar[i], br[j], acc[i][j]);
        }
        __syncthreads();   // everyone done with old G (read in P step) — safe to overwrite
#pragma unroll
        for (int i = 0; i < 4; ++i) {
            int s = (ty << 2) + i;
#pragma unroll
            for (int j = 0; j < 4; ++j) {
                int t = (tx << 2) + j;
                sm.G[s][t] = (t <= s) ? acc[i][j] : 0.f;
            }
        }
    }
    __syncthreads();

    // O[s][d] = sum_t W[s][t]*V[t][d] + sum_c P[s][c]*A0v[c][d]
    {
        float acc[4][4];
#pragma unroll
        for (int i = 0; i < 4; ++i)
#pragma unroll
            for (int j = 0; j < 4; ++j) acc[i][j] = 0.f;
        for (int t = 0; t < CHUNK; ++t) {
            float ar[4], br[4];
#pragma unroll
            for (int i = 0; i < 4; ++i) ar[i] = sm.G[(ty << 2) + i][t];
#pragma unroll
            for (int j = 0; j < 4; ++j) br[j] = sm.Vs[t][(tx << 2) + j];
#pragma unroll
            for (int i = 0; i < 4; ++i)
#pragma unroll
                for (int j = 0; j < 4; ++j) acc[i][j] = fmaf(ar[i], br[j], acc[i][j]);
        }
        for (int c = 0; c < NC; ++c) {
            float ar[4], br[4];
#pragma unroll
            for (int i = 0; i < 4; ++i) ar[i] = sm.P[(ty << 2) + i][c];
#pragma unroll
            for (int j = 0; j < 4; ++j) br[j] = sm.A0v[c][(tx << 2) + j];
#pragma unroll
            for (int i = 0; i < 4; ++i)
#pragma unroll
                for (int j = 0; j < 4; ++j) acc[i][j] = fmaf(ar[i], br[j], acc[i][j]);
        }
#pragma unroll
        for (int i = 0; i < 4; ++i) {
            int s = (ty << 2) + i;
#pragma unroll
            for (int j = 0; j < 4; ++j) {
                int d = (tx << 2) + j;
                g_O[(size_t)(s0 + s) * DMODEL + h * DHEAD + d] = acc[i][j];
            }
        }
    }
}

// ---------------- launch -----------------------------------------------
extern "C" void kernel_launch(void* const* d_in, const int* in_sizes, int n_in,
                              void* d_out, int out_size)
{
    const float* x    = (const float*)d_in[0];
    const float* q_c  = (const float*)d_in[1];
    const float* beta = (const float*)d_in[2];
    const float* Wq   = (const float*)d_in[3];
    const float* bq   = (const float*)d_in[4];
    const float* Wk   = (const float*)d_in[5];
    const float* bk   = (const float*)d_in[6];
    const float* Wv   = (const float*)d_in[7];
    const float* bv   = (const float*)d_in[8];
    const float* Wo   = (const float*)d_in[9];
    const float* bo   = (const float*)d_in[10];
    float* out = (float*)d_out;

    static bool attrs_set = false;
    if (!attrs_set) {
        cudaFuncSetAttribute(attn_kernel, cudaFuncAttributeMaxDynamicSharedMemorySize,
                             (int)sizeof(K6Smem));
        cudaFuncSetAttribute(chunksum_kernel, cudaFuncAttributeMaxDynamicSharedMemorySize,
                             (int)sizeof(ChunkSmem));
        attrs_set = true;
    }

    init_rowmax_kernel<<<1, NHEAD * NC>>>();
    gemm_qkv_kernel<<<dim3(8, 8, 3), 256>>>(x, Wq, bq, Wk, bk, Wv, bv);
    cw_kernel<<<dim3(NCHUNK, NHEAD), 256>>>(q_c);
    exp_kernel<<<(NHEAD * NC * SLEN) / 256, 256>>>();
    chunksum_kernel<<<dim3(NCHUNK, NHEAD), 256, sizeof(ChunkSmem)>>>();
    prefix_kernel<<<NHEAD, 256>>>();
    attn_kernel<<<dim3(NCHUNK, NHEAD), 256, sizeof(K6Smem)>>>(beta);
    gemm_out_kernel<<<dim3(8, 8), 256>>>(Wo, bo, out);
}